// round 1
// baseline (speedup 1.0000x reference)
#include <cuda_runtime.h>
#include <cstdint>
#include <cstddef>

// VectorQuantizer on GB300 (sm_103a)
// z_e: (16,256,64,64) fp32 ; embedding: (1024,256) fp32
// out: z_q_st (16,256,64,64) fp32 [+ vq_loss scalar at index NC if present]

#define NEMB 1024
#define EDIM 256
#define HW   4096          // 64*64, pixels per batch plane
#define NPIX 65536         // 16 * 4096
#define NC   16777216      // NPIX * EDIM

// ---- scratch (device globals; no allocation allowed) ----
__device__ __align__(16) float  g_e2[NEMB];
__device__ int    g_idx[NPIX];
__device__ double g_part[2048];

// ---- packed f32x2 helpers ----
#define FMA2(d, a, b) asm("fma.rn.f32x2 %0, %1, %2, %0;" : "+l"(d) : "l"(a), "l"(b))

static __device__ __forceinline__ unsigned long long pack2(float x) {
    unsigned long long r;
    unsigned int u = __float_as_uint(x);
    asm("mov.b64 %0, {%1, %1};" : "=l"(r) : "r"(u));
    return r;
}
static __device__ __forceinline__ void unpack2(unsigned long long v, float& lo, float& hi) {
    unsigned int a, b;
    asm("mov.b64 {%0, %1}, %2;" : "=r"(a), "=r"(b) : "l"(v));
    lo = __uint_as_float(a);
    hi = __uint_as_float(b);
}

// ============================================================
// K1: per-code squared norms. One warp per code.
// ============================================================
__global__ void k_e2(const float* __restrict__ emb) {
    int warp = (blockIdx.x * blockDim.x + threadIdx.x) >> 5;
    int lane = threadIdx.x & 31;
    if (warp >= NEMB) return;
    const float4* row = reinterpret_cast<const float4*>(emb + (size_t)warp * EDIM);
    float s = 0.f;
    #pragma unroll
    for (int i = lane; i < EDIM / 4; i += 32) {
        float4 v = row[i];
        s += v.x * v.x + v.y * v.y + v.z * v.z + v.w * v.w;
    }
    #pragma unroll
    for (int o = 16; o; o >>= 1) s += __shfl_xor_sync(0xFFFFFFFFu, s, o);
    if (lane == 0) g_e2[warp] = s;
}

// ============================================================
// K2: fused GEMM + argmin.
// Tile: 128 pixels x 128 codes per CTA, K chunked by 16, double-buffered.
// Thread tile: 8 pixels x 8 codes as 32 f32x2 accumulators (code pairs).
// score(code) = ||e||^2 - 2 * x.e  (||x||^2 is row-constant).
// ============================================================
__global__ __launch_bounds__(256, 2)
void k_argmin(const float* __restrict__ z, const float* __restrict__ emb) {
    __shared__ float sA[2][16][128];   // [buf][k][pixel]
    __shared__ float sB[2][16][128];   // [buf][k][code]

    const int t  = threadIdx.x;
    const int tx = t & 15;             // -> 8 codes  (tx*8 .. tx*8+7)
    const int ty = t >> 4;             // -> 8 pixels (ty*8 .. ty*8+7)

    const int pix0 = blockIdx.x << 7;                 // 128-pixel tile, never straddles a batch plane
    const float* zb = z + (((size_t)(pix0 >> 12)) << 20) + (pix0 & 4095);

    // A loader: 16 rows (channels) x 128 pixels per chunk; 8 floats/thread
    const int la_c = t >> 4;
    const int la_p = (t & 15) << 3;
    // B loader: 128 codes x 16 k per chunk; 8 floats/thread, stored transposed
    const int lb_code = t >> 1;
    const int lb_k0   = (t & 1) << 3;

    float bestv[8];
    int   besti[8];
    #pragma unroll
    for (int i = 0; i < 8; ++i) { bestv[i] = 3.4e38f; besti[i] = 0; }

    for (int cc = 0; cc < 8; ++cc) {
        const int code0 = cc << 7;

        unsigned long long acc[8][4];
        #pragma unroll
        for (int i = 0; i < 8; ++i)
            #pragma unroll
            for (int j = 0; j < 4; ++j) acc[i][j] = 0ULL;

        // ---- preload chunk 0 into buffer 0 ----
        {
            const float* sa = zb + (size_t)la_c * HW + la_p;
            float4 v0 = *reinterpret_cast<const float4*>(sa);
            float4 v1 = *reinterpret_cast<const float4*>(sa + 4);
            *reinterpret_cast<float4*>(&sA[0][la_c][la_p])     = v0;
            *reinterpret_cast<float4*>(&sA[0][la_c][la_p + 4]) = v1;

            const float* sb = emb + (size_t)(code0 + lb_code) * EDIM + lb_k0;
            float4 w0 = *reinterpret_cast<const float4*>(sb);
            float4 w1 = *reinterpret_cast<const float4*>(sb + 4);
            float tmp[8] = {w0.x, w0.y, w0.z, w0.w, w1.x, w1.y, w1.z, w1.w};
            #pragma unroll
            for (int j = 0; j < 8; ++j) sB[0][lb_k0 + j][lb_code] = tmp[j];
        }
        __syncthreads();

        int buf = 0;
        for (int kb = 0; kb < 16; ++kb) {
            // issue next chunk's loads into the other buffer (overlaps compute)
            if (kb < 15) {
                const int kbase = (kb + 1) << 4;
                const float* sa = zb + (size_t)(kbase + la_c) * HW + la_p;
                float4 v0 = *reinterpret_cast<const float4*>(sa);
                float4 v1 = *reinterpret_cast<const float4*>(sa + 4);
                *reinterpret_cast<float4*>(&sA[buf ^ 1][la_c][la_p])     = v0;
                *reinterpret_cast<float4*>(&sA[buf ^ 1][la_c][la_p + 4]) = v1;

                const float* sb = emb + (size_t)(code0 + lb_code) * EDIM + kbase + lb_k0;
                float4 w0 = *reinterpret_cast<const float4*>(sb);
                float4 w1 = *reinterpret_cast<const float4*>(sb + 4);
                float tmp[8] = {w0.x, w0.y, w0.z, w0.w, w1.x, w1.y, w1.z, w1.w};
                #pragma unroll
                for (int j = 0; j < 8; ++j) sB[buf ^ 1][lb_k0 + j][lb_code] = tmp[j];
            }

            // ---- compute on current buffer ----
            #pragma unroll
            for (int kk = 0; kk < 16; ++kk) {
                float4 a0 = *reinterpret_cast<const float4*>(&sA[buf][kk][ty << 3]);
                float4 a1 = *reinterpret_cast<const float4*>(&sA[buf][kk][(ty << 3) + 4]);
                ulonglong2 b01 = *reinterpret_cast<const ulonglong2*>(&sB[buf][kk][tx << 3]);
                ulonglong2 b23 = *reinterpret_cast<const ulonglong2*>(&sB[buf][kk][(tx << 3) + 4]);
                unsigned long long bv[4] = {b01.x, b01.y, b23.x, b23.y};
                unsigned long long aa[8];
                aa[0] = pack2(a0.x); aa[1] = pack2(a0.y);
                aa[2] = pack2(a0.z); aa[3] = pack2(a0.w);
                aa[4] = pack2(a1.x); aa[5] = pack2(a1.y);
                aa[6] = pack2(a1.z); aa[7] = pack2(a1.w);
                #pragma unroll
                for (int i = 0; i < 8; ++i)
                    #pragma unroll
                    for (int j = 0; j < 4; ++j)
                        FMA2(acc[i][j], aa[i], bv[j]);
            }
            __syncthreads();
            buf ^= 1;
        }

        // ---- epilogue: scores + running argmin (codes ascending for tie-break) ----
        float4 e2a = *reinterpret_cast<const float4*>(&g_e2[code0 + (tx << 3)]);
        float4 e2b = *reinterpret_cast<const float4*>(&g_e2[code0 + (tx << 3) + 4]);
        float e2v[8] = {e2a.x, e2a.y, e2a.z, e2a.w, e2b.x, e2b.y, e2b.z, e2b.w};
        #pragma unroll
        for (int i = 0; i < 8; ++i) {
            #pragma unroll
            for (int j = 0; j < 4; ++j) {
                float lo, hi;
                unpack2(acc[i][j], lo, hi);
                float s0 = e2v[2 * j]     - 2.f * lo;
                float s1 = e2v[2 * j + 1] - 2.f * hi;
                int c = code0 + (tx << 3) + 2 * j;
                if (s0 < bestv[i]) { bestv[i] = s0; besti[i] = c; }
                if (s1 < bestv[i]) { bestv[i] = s1; besti[i] = c + 1; }
            }
        }
    }

    // cross-thread argmin over tx (16-lane halves of each warp), lowest index wins ties
    #pragma unroll
    for (int o = 8; o; o >>= 1) {
        #pragma unroll
        for (int i = 0; i < 8; ++i) {
            float ov = __shfl_xor_sync(0xFFFFFFFFu, bestv[i], o);
            int   oi = __shfl_xor_sync(0xFFFFFFFFu, besti[i], o);
            if (ov < bestv[i] || (ov == bestv[i] && oi < besti[i])) {
                bestv[i] = ov; besti[i] = oi;
            }
        }
    }
    if (tx == 0) {
        #pragma unroll
        for (int i = 0; i < 8; ++i) g_idx[pix0 + (ty << 3) + i] = besti[i];
    }
}

// ============================================================
// K3: gather z_q, write z_q_st = z_e + (z_q - z_e) (reference op order),
// accumulate commitment-loss partial per block. 32 pixels / CTA.
// ============================================================
__global__ __launch_bounds__(256)
void k_gather(const float* __restrict__ z, const float* __restrict__ emb,
              float* __restrict__ out) {
    __shared__ float sE[32 * 260];          // 260-float row pitch: conflict-free, 16B-aligned rows
    __shared__ float swarp[8];

    const int t = threadIdx.x;
    const int pix0 = blockIdx.x << 5;

    // stage 32 codebook rows (coalesced reads from embedding)
    #pragma unroll
    for (int it = 0; it < 8; ++it) {
        int slot = t + (it << 8);           // 0..2047 float4 slots
        int p  = slot >> 6;                 // pixel 0..31
        int c4 = slot & 63;                 // float4 column 0..63
        int idx = g_idx[pix0 + p];
        float4 v = *reinterpret_cast<const float4*>(emb + (size_t)idx * EDIM + (c4 << 2));
        *reinterpret_cast<float4*>(&sE[p * 260 + (c4 << 2)]) = v;
    }
    __syncthreads();

    const float* zb = z   + (((size_t)(pix0 >> 12)) << 20) + (pix0 & 4095);
    float*       ob = out + (((size_t)(pix0 >> 12)) << 20) + (pix0 & 4095);

    float lsum = 0.f;
    #pragma unroll
    for (int it = 0; it < 8; ++it) {
        int slot = t + (it << 8);
        int hw = slot & 31;                 // lane-contiguous -> coalesced gmem
        int c4 = slot >> 5;                 // 0..63
        float4 e = *reinterpret_cast<const float4*>(&sE[hw * 260 + (c4 << 2)]);
        float ev[4] = {e.x, e.y, e.z, e.w};
        #pragma unroll
        for (int j = 0; j < 4; ++j) {
            size_t g = (size_t)((c4 << 2) + j) * HW + hw;
            float ze = zb[g];
            float d  = ev[j] - ze;          // stop_grad(z_q - z_e)
            ob[g] = ze + d;                 // straight-through value
            lsum += d * d;
        }
    }

    // deterministic block reduction -> double partial
    #pragma unroll
    for (int o = 16; o; o >>= 1) lsum += __shfl_xor_sync(0xFFFFFFFFu, lsum, o);
    if ((t & 31) == 0) swarp[t >> 5] = lsum;
    __syncthreads();
    if (t == 0) {
        double s = 0.0;
        #pragma unroll
        for (int w = 0; w < 8; ++w) s += (double)swarp[w];
        g_part[blockIdx.x] = s;
    }
}

// ============================================================
// K4: deterministic reduction of 2048 partials -> vq_loss scalar
// ============================================================
__global__ void k_loss(float* __restrict__ out, int out_size) {
    __shared__ double sd[256];
    int t = threadIdx.x;
    double s = 0.0;
    for (int i = t; i < 2048; i += 256) s += g_part[i];
    sd[t] = s;
    __syncthreads();
    for (int o = 128; o; o >>= 1) {
        if (t < o) sd[t] += sd[t + o];
        __syncthreads();
    }
    if (t == 0 && out_size > NC)
        out[NC] = (float)(0.25 * sd[0] / (double)NC);
}

// ============================================================
extern "C" void kernel_launch(void* const* d_in, const int* in_sizes, int n_in,
                              void* d_out, int out_size) {
    const float* z   = (const float*)d_in[0];   // z_e  (16,256,64,64)
    const float* emb = (const float*)d_in[1];   // embedding (1024,256)
    float* out = (float*)d_out;

    k_e2    <<<128,  256>>>(emb);
    k_argmin<<<512,  256>>>(z, emb);
    k_gather<<<2048, 256>>>(z, emb, out);
    k_loss  <<<1,    256>>>(out, out_size);
}